// round 7
// baseline (speedup 1.0000x reference)
#include <cuda_runtime.h>
#include <cuda_bf16.h>

// Problem constants
#define Wd 192
#define Hd 192
#define Dd 128
#define Bd 2
#define TX 32
#define TY 8
#define VX 2                    // voxels per thread along W (f32x2 packing)
#define TILE_W (TX * VX)        // 64
#define DCHUNK 8
#define SROW2 68                // TILE_W + 2 halo, padded (even -> 8B-aligned pairs)
#define PLANE2 ((TY + 2) * SROW2)   // 10 * 68 = 680 floats per z-plane

typedef unsigned long long ull;

// ---- packed f32x2 helpers (Blackwell sm_103a) ----
__device__ __forceinline__ ull pack2(float lo, float hi) {
    ull r; asm("mov.b64 %0,{%1,%2};" : "=l"(r) : "f"(lo), "f"(hi)); return r;
}
__device__ __forceinline__ ull fma2(ull a, ull b, ull c) {
    ull d; asm("fma.rn.f32x2 %0,%1,%2,%3;" : "=l"(d) : "l"(a), "l"(b), "l"(c)); return d;
}
__device__ __forceinline__ ull add2(ull a, ull b) {
    ull d; asm("add.rn.f32x2 %0,%1,%2;" : "=l"(d) : "l"(a), "l"(b)); return d;
}
__device__ __forceinline__ float lo2(ull a) { return __uint_as_float((unsigned)(a & 0xffffffffull)); }
__device__ __forceinline__ float hi2(ull a) { return __uint_as_float((unsigned)(a >> 32)); }

// Range-kernel constant: -log2(e) / (2 * 1.2^2)
#define KRC  (-0.50093579f)
// Spatial step in exponent: -log2(e) / (2 * 120^2)
#define KSC  (-5.0093579e-5f)
// Poly center shift: u = arg + 0.2505  (expansion point x0 = -0.2505)
#define X0S  (0.2505f)

// Degree-3 economized Taylor of 2^x about x0=-0.2505, in u = x - x0, |u| <= 0.2505.
// p(u) = ((C3*u + C2)*u + C1)*u + C0, max abs err ~5e-6 on [-0.501, 0].
#define PC0 0.8406010f
#define PC1 0.5826630f
#define PC2 0.2024430f
#define PC3 0.0466570f

__global__ __launch_bounds__(TX * TY)
void bilat3d_kernel(const float* __restrict__ in, float* __restrict__ out) {
    __shared__ __align__(16) float sm[3 * PLANE2];

    const int tx  = threadIdx.x;
    const int ty  = threadIdx.y;
    const int tid = ty * TX + tx;
    const int w0  = blockIdx.x * TILE_W;
    const int h0  = blockIdx.y * TY;
    const int bz  = blockIdx.z;
    const int b      = bz / (Dd / DCHUNK);
    const int dstart = (bz % (Dd / DCHUNK)) * DCHUNK;

    const float* base = in + (size_t)b * Dd * Hd * Wd;

    // Load one z-plane (replicate-padded halo) into a smem slot.
    auto loadPlane = [&](int d, int slot) {
        d = min(max(d, 0), Dd - 1);
        const float* p = base + (size_t)d * Hd * Wd;
        #pragma unroll
        for (int i = tid; i < PLANE2; i += TX * TY) {
            int r  = i / SROW2;
            int c  = i - r * SROW2;
            int gh = min(max(h0 + r - 1, 0), Hd - 1);
            int gw = min(max(w0 + c - 1, 0), Wd - 1);
            sm[slot * PLANE2 + i] = p[gh * Wd + gw];
        }
    };

    loadPlane(dstart - 1, 0);
    loadPlane(dstart,     1);
    int s0 = 0, s1 = 1, s2 = 2;

    // Packed constants (loop-invariant)
    const ull KR2 = pack2(KRC, KRC);
    const ull C0v = pack2(PC0, PC0);
    const ull C1v = pack2(PC1, PC1);
    const ull C2v = pack2(PC2, PC2);
    const ull C3v = pack2(PC3, PC3);

    for (int dd = 0; dd < DCHUNK; ++dd) {
        loadPlane(dstart + dd + 1, s2);
        __syncthreads();

        // Centers for the two voxels this thread owns (local cols 2tx+1, 2tx+2)
        const int ci = s1 * PLANE2 + (ty + 1) * SROW2 + 2 * tx;
        const float cA = sm[ci + 1];
        const float cB = sm[ci + 2];

        // arg+X0S = KR*(n-c)^2 + ks + X0S = (KR*n + B)*n + C
        //   B = -2*KR*c,  C = KR*c^2 + ks + X0S   (ks = dist^2 * KSC)
        const ull B2 = pack2((-2.0f * KRC) * cA, (-2.0f * KRC) * cB);
        const float ccA = fmaf(KRC * cA, cA, X0S);
        const float ccB = fmaf(KRC * cB, cB, X0S);
        ull Cd[4];
        {
            float a = ccA, bb = ccB;
            Cd[0] = pack2(a, bb); a += KSC; bb += KSC;
            Cd[1] = pack2(a, bb); a += KSC; bb += KSC;
            Cd[2] = pack2(a, bb); a += KSC; bb += KSC;
            Cd[3] = pack2(a, bb);
        }

        ull num = pack2(0.0f, 0.0f);
        ull den = pack2(0.0f, 0.0f);

        const int b0 = s0 * PLANE2, b1 = s1 * PLANE2, b2s = s2 * PLANE2;
        const int rowoff = 2 * tx;

        #pragma unroll
        for (int zi = 0; zi < 3; ++zi) {
            const int sb = (zi == 0 ? b0 : (zi == 1 ? b1 : b2s));
            #pragma unroll
            for (int yi = 0; yi < 3; ++yi) {
                const float* rp = &sm[sb + (ty + yi) * SROW2 + rowoff];
                // aligned LDS.64 pairs: cols (2tx,2tx+1) and (2tx+2,2tx+3)
                const ull qa = *(const ull*)rp;         // xi = -1 pair
                const ull qc = *(const ull*)(rp + 2);   // xi = +1 pair
                const ull qb = pack2(hi2(qa), lo2(qc)); // xi = 0 pair (register repack)

                const int dyz = (zi - 1) * (zi - 1) + (yi - 1) * (yi - 1);
                const ull Cmid  = Cd[dyz];
                const ull Cside = Cd[dyz + 1];

                // --- xi = -1 ---
                {
                    ull t = fma2(KR2, qa, B2);
                    ull u = fma2(t,  qa, Cside);
                    ull p = fma2(C3v, u, C2v);
                    p = fma2(p, u, C1v);
                    p = fma2(p, u, C0v);
                    num = fma2(p, qa, num);
                    den = add2(den, p);
                }
                // --- xi = 0 ---
                {
                    ull t = fma2(KR2, qb, B2);
                    ull u = fma2(t,  qb, Cmid);
                    ull p = fma2(C3v, u, C2v);
                    p = fma2(p, u, C1v);
                    p = fma2(p, u, C0v);
                    num = fma2(p, qb, num);
                    den = add2(den, p);
                }
                // --- xi = +1 ---
                {
                    ull t = fma2(KR2, qc, B2);
                    ull u = fma2(t,  qc, Cside);
                    ull p = fma2(C3v, u, C2v);
                    p = fma2(p, u, C1v);
                    p = fma2(p, u, C0v);
                    num = fma2(p, qc, num);
                    den = add2(den, p);
                }
            }
        }

        const int d = dstart + dd;
        float2 o;
        o.x = __fdividef(lo2(num), lo2(den));  // den >= ~0.84 always (center weight)
        o.y = __fdividef(hi2(num), hi2(den));
        *(float2*)&out[((size_t)(b * Dd + d) * Hd + (h0 + ty)) * Wd + (w0 + 2 * tx)] = o;

        __syncthreads();           // protect slot reuse before next plane load
        int t = s0; s0 = s1; s1 = s2; s2 = t;
    }
}

extern "C" void kernel_launch(void* const* d_in, const int* in_sizes, int n_in,
                              void* d_out, int out_size) {
    const float* vol = (const float*)d_in[0];
    float* out = (float*)d_out;
    dim3 grid(Wd / TILE_W, Hd / TY, Bd * (Dd / DCHUNK));  // 3 x 24 x 32 = 2304 CTAs
    dim3 block(TX, TY);                                    // 256 threads
    bilat3d_kernel<<<grid, block>>>(vol, out);
}

// round 8
// speedup vs baseline: 1.1424x; 1.1424x over previous
#include <cuda_runtime.h>
#include <cuda_bf16.h>

// Problem constants
#define Wd 192
#define Hd 192
#define Dd 128
#define Bd 2
#define TX 32
#define TY 8
#define NT (TX * TY)            // 256 threads
#define TILE_W (TX * 2)         // 64 (2 voxels per thread, f32x2)
#define DCHUNK 8
#define SROW2 68                // TILE_W + 2 halo, even -> 8B-aligned pairs
#define PLANE2 ((TY + 2) * SROW2)   // 680 floats per z-plane

typedef unsigned long long ull;

// ---- packed f32x2 helpers (Blackwell sm_103a) ----
__device__ __forceinline__ ull pack2(float lo, float hi) {
    ull r; asm("mov.b64 %0,{%1,%2};" : "=l"(r) : "f"(lo), "f"(hi)); return r;
}
__device__ __forceinline__ void unpack2(ull v, float& lo, float& hi) {
    asm("mov.b64 {%0,%1},%2;" : "=f"(lo), "=f"(hi) : "l"(v));
}
__device__ __forceinline__ ull fma2(ull a, ull b, ull c) {
    ull d; asm("fma.rn.f32x2 %0,%1,%2,%3;" : "=l"(d) : "l"(a), "l"(b), "l"(c)); return d;
}
__device__ __forceinline__ ull add2(ull a, ull b) {
    ull d; asm("add.rn.f32x2 %0,%1,%2;" : "=l"(d) : "l"(a), "l"(b)); return d;
}
__device__ __forceinline__ float ex2f(float x) {
    float y; asm("ex2.approx.ftz.f32 %0, %1;" : "=f"(y) : "f"(x)); return y;
}

// Range-kernel constant: -log2(e) / (2 * 1.2^2)
#define KRC  (-0.50093579f)
// Spatial step in exponent: -log2(e) / (2 * 120^2)
#define KSC  (-5.0093579e-5f)
// Poly expansion shift: u = arg + 0.2505
#define X0S  (0.2505f)
// Degree-3 economized Taylor of 2^x about x0=-0.2505; |u|<=0.2505, abs err ~5e-6
#define PC0 0.8406010f
#define PC1 0.5826630f
#define PC2 0.2024430f
#define PC3 0.0466570f

__global__ __launch_bounds__(NT, 6)
void bilat3d_kernel(const float* __restrict__ in, float* __restrict__ out) {
    __shared__ __align__(16) float sm[3 * PLANE2];

    const int tx  = threadIdx.x;
    const int ty  = threadIdx.y;
    const int tid = ty * TX + tx;
    const int w0  = blockIdx.x * TILE_W;
    const int h0  = blockIdx.y * TY;
    const int bz  = blockIdx.z;
    const int b      = bz / (Dd / DCHUNK);
    const int dstart = (bz % (Dd / DCHUNK)) * DCHUNK;

    const float* base = in + (size_t)b * Dd * Hd * Wd;

    // ---- dd-invariant halo-gather offsets (3 strided assignments/thread) ----
    auto gOff = [&](int i) {
        int r  = i / SROW2, c = i - r * SROW2;
        int gh = min(max(h0 + r - 1, 0), Hd - 1);
        int gw = min(max(w0 + c - 1, 0), Wd - 1);
        return gh * Wd + gw;
    };
    const int  i0 = tid, i1 = tid + NT, i2 = tid + 2 * NT;
    const bool p2 = (i2 < PLANE2);
    const int  go0 = gOff(i0), go1 = gOff(i1), go2 = p2 ? gOff(i2) : 0;

    auto planePtr = [&](int d) {
        d = min(max(d, 0), Dd - 1);
        return base + (size_t)d * Hd * Wd;
    };

    // Prolog: fill slots 0,1,2 with planes dstart-1, dstart, dstart+1
    #pragma unroll
    for (int s = 0; s < 3; ++s) {
        const float* p = planePtr(dstart - 1 + s);
        sm[s * PLANE2 + i0] = p[go0];
        sm[s * PLANE2 + i1] = p[go1];
        if (p2) sm[s * PLANE2 + i2] = p[go2];
    }
    __syncthreads();
    int s0 = 0, s1 = 1, s2 = 2;

    // Packed loop-invariant constants
    const ull KR2 = pack2(KRC, KRC);
    const ull C0v = pack2(PC0, PC0);
    const ull C1v = pack2(PC1, PC1);
    const ull C2v = pack2(PC2, PC2);
    const ull C3v = pack2(PC3, PC3);

    for (int dd = 0; dd < DCHUNK; ++dd) {
        // Prefetch plane z+2 into registers (overlaps with compute below)
        const float* pn = planePtr(dstart + dd + 2);
        const float r0 = pn[go0];
        const float r1 = pn[go1];
        const float r2 = p2 ? pn[go2] : 0.0f;

        // Centers (local cols 2tx+1, 2tx+2 of middle plane)
        const int ci = s1 * PLANE2 + (ty + 1) * SROW2 + 2 * tx;
        const float cA = sm[ci + 1];
        const float cB = sm[ci + 2];

        // arg(+shift) = (KR*n + B)*n + C;  B = -2*KR*c
        const ull B2 = pack2((-2.0f * KRC) * cA, (-2.0f * KRC) * cB);
        const float cc0A = KRC * cA * cA;       // mufu path C (no shift)
        const float cc0B = KRC * cB * cB;
        ull Cp[3], Cm[4];                        // poly: dist 0..2; mufu: dist 1..3
        {
            float a = cc0A, bb = cc0B;
            Cp[0] = pack2(a + X0S, bb + X0S);
            a += KSC; bb += KSC;
            Cp[1] = pack2(a + X0S, bb + X0S);  Cm[1] = pack2(a, bb);
            a += KSC; bb += KSC;
            Cp[2] = pack2(a + X0S, bb + X0S);  Cm[2] = pack2(a, bb);
            a += KSC; bb += KSC;
            Cm[3] = pack2(a, bb);
        }

        ull num = 0ull, den = 0ull;

        const int b0 = s0 * PLANE2, b1 = s1 * PLANE2, b2s = s2 * PLANE2;
        const int rowoff = 2 * tx;

        #pragma unroll
        for (int zi = 0; zi < 3; ++zi) {
            const int sb = (zi == 0 ? b0 : (zi == 1 ? b1 : b2s));
            #pragma unroll
            for (int yi = 0; yi < 3; ++yi) {
                const float* rp = &sm[sb + (ty + yi) * SROW2 + rowoff];
                const ull qa = *(const ull*)rp;        // xi=-1 pair (LDS.64)
                const ull qc = *(const ull*)(rp + 2);  // xi=+1 pair (LDS.64)
                float qaL, qaH, qcL, qcH;
                unpack2(qa, qaL, qaH);
                unpack2(qc, qcL, qcH);
                const ull qb = pack2(qaH, qcL);        // xi=0 pair (register alias)

                const int dyz = (zi - 1) * (zi - 1) + (yi - 1) * (yi - 1);

                // --- xi = 0 : polynomial path (fma pipe) ---
                {
                    ull t = fma2(KR2, qb, B2);
                    ull u = fma2(t,  qb, Cp[dyz]);
                    ull p = fma2(C3v, u, C2v);
                    p = fma2(p, u, C1v);
                    p = fma2(p, u, C0v);
                    num = fma2(p, qb, num);
                    den = add2(den, p);
                }
                // --- xi = -1 : MUFU path ---
                {
                    ull t = fma2(KR2, qa, B2);
                    ull u = fma2(t,  qa, Cm[dyz + 1]);
                    float uL, uH; unpack2(u, uL, uH);
                    ull w = pack2(ex2f(uL), ex2f(uH));
                    num = fma2(w, qa, num);
                    den = add2(den, w);
                }
                // --- xi = +1 : MUFU path ---
                {
                    ull t = fma2(KR2, qc, B2);
                    ull u = fma2(t,  qc, Cm[dyz + 1]);
                    float uL, uH; unpack2(u, uL, uH);
                    ull w = pack2(ex2f(uL), ex2f(uH));
                    num = fma2(w, qc, num);
                    den = add2(den, w);
                }
            }
        }

        const int d = dstart + dd;
        float nL, nH, dL, dH;
        unpack2(num, nL, nH);
        unpack2(den, dL, dH);
        float2 o;
        o.x = __fdividef(nL, dL);   // den >= ~0.84 always (center weight)
        o.y = __fdividef(nH, dH);
        *(float2*)&out[((size_t)(b * Dd + d) * Hd + (h0 + ty)) * Wd + (w0 + 2 * tx)] = o;

        __syncthreads();            // all reads of slot s0 complete
        // Commit prefetched plane z+2 into the retiring slot
        sm[s0 * PLANE2 + i0] = r0;
        sm[s0 * PLANE2 + i1] = r1;
        if (p2) sm[s0 * PLANE2 + i2] = r2;
        __syncthreads();

        int t = s0; s0 = s1; s1 = s2; s2 = t;
    }
}

extern "C" void kernel_launch(void* const* d_in, const int* in_sizes, int n_in,
                              void* d_out, int out_size) {
    const float* vol = (const float*)d_in[0];
    float* out = (float*)d_out;
    dim3 grid(Wd / TILE_W, Hd / TY, Bd * (Dd / DCHUNK));  // 3 x 24 x 32 = 2304 CTAs
    dim3 block(TX, TY);                                    // 256 threads
    bilat3d_kernel<<<grid, block>>>(vol, out);
}

// round 9
// speedup vs baseline: 1.1492x; 1.0060x over previous
#include <cuda_runtime.h>
#include <cuda_bf16.h>

// Problem constants
#define Wd 192
#define Hd 192
#define Dd 128
#define Bd 2
#define TX 32
#define TY 8
#define NT (TX * TY)            // 256 threads
#define TILE_W (TX * 2)         // 64 (2 voxels per thread, f32x2)
#define DCHUNK 8
#define SROW2 68                // TILE_W + 2 halo, even -> 8B-aligned pairs
#define PLANE2 ((TY + 2) * SROW2)   // 680 floats per z-plane
#define NSLOT 4                 // ring depth (period 4 -> compile-time slots)

typedef unsigned long long ull;

// ---- packed f32x2 helpers (Blackwell sm_103a) ----
__device__ __forceinline__ ull pack2(float lo, float hi) {
    ull r; asm("mov.b64 %0,{%1,%2};" : "=l"(r) : "f"(lo), "f"(hi)); return r;
}
__device__ __forceinline__ void unpack2(ull v, float& lo, float& hi) {
    asm("mov.b64 {%0,%1},%2;" : "=f"(lo), "=f"(hi) : "l"(v));
}
__device__ __forceinline__ ull fma2(ull a, ull b, ull c) {
    ull d; asm("fma.rn.f32x2 %0,%1,%2,%3;" : "=l"(d) : "l"(a), "l"(b), "l"(c)); return d;
}
__device__ __forceinline__ ull add2(ull a, ull b) {
    ull d; asm("add.rn.f32x2 %0,%1,%2;" : "=l"(d) : "l"(a), "l"(b)); return d;
}
__device__ __forceinline__ float ex2f(float x) {
    float y; asm("ex2.approx.ftz.f32 %0, %1;" : "=f"(y) : "f"(x)); return y;
}

// Range-kernel constant: -log2(e) / (2 * 1.2^2)
#define KRC  (-0.50093579f)
// Spatial step in exponent: -log2(e) / (2 * 120^2)
#define KSC  (-5.0093579e-5f)
// Poly expansion shift: u = arg + 0.2505
#define X0S  (0.2505f)
// Degree-3 economized Taylor of 2^x about x0=-0.2505; |u|<=0.2505, abs err ~5e-6
#define PC0 0.8406010f
#define PC1 0.5826630f
#define PC2 0.2024430f
#define PC3 0.0466570f

__global__ __launch_bounds__(NT, 7)
void bilat3d_kernel(const float* __restrict__ in, float* __restrict__ out) {
    __shared__ __align__(16) float sm[NSLOT * PLANE2];

    const int tx  = threadIdx.x;
    const int ty  = threadIdx.y;
    const int tid = ty * TX + tx;
    const int w0  = blockIdx.x * TILE_W;
    const int h0  = blockIdx.y * TY;
    const int bz  = blockIdx.z;
    const int b      = bz / (Dd / DCHUNK);
    const int dstart = (bz % (Dd / DCHUNK)) * DCHUNK;

    const float* base = in + (size_t)b * Dd * Hd * Wd;

    // ---- dd-invariant halo-gather offsets ----
    auto gOff = [&](int i) {
        int r  = i / SROW2, c = i - r * SROW2;
        int gh = min(max(h0 + r - 1, 0), Hd - 1);
        int gw = min(max(w0 + c - 1, 0), Wd - 1);
        return gh * Wd + gw;
    };
    const int  i0 = tid, i1 = tid + NT, i2 = tid + 2 * NT;
    const bool p2 = (i2 < PLANE2);
    const int  go0 = gOff(i0), go1 = gOff(i1), go2 = p2 ? gOff(i2) : 0;

    auto planePtr = [&](int d) {
        d = min(max(d, 0), Dd - 1);
        return base + (size_t)d * Hd * Wd;
    };

    // Prolog: slots 0,1,2 <- planes dstart-1, dstart, dstart+1
    #pragma unroll
    for (int s = 0; s < 3; ++s) {
        const float* p = planePtr(dstart - 1 + s);
        sm[s * PLANE2 + i0] = p[go0];
        sm[s * PLANE2 + i1] = p[go1];
        if (p2) sm[s * PLANE2 + i2] = p[go2];
    }
    __syncthreads();

    // Loop-invariant packed constants
    const ull KR2  = pack2(KRC, KRC);
    const ull KS2  = pack2(KSC, KSC);
    const ull X0S2 = pack2(X0S, X0S);
    const ull C0v = pack2(PC0, PC0);
    const ull C1v = pack2(PC1, PC1);
    const ull C2v = pack2(PC2, PC2);
    const ull C3v = pack2(PC3, PC3);

    const float* rb = sm + ty * SROW2 + 2 * tx;   // per-thread row base (col 2tx)
    float* outp = out + ((size_t)(b * Dd + dstart) * Hd + (h0 + ty)) * Wd
                      + (w0 + 2 * tx);

    // One dd step. S0..S3 are compile-time after inlining: LDS offsets become
    // immediates, no slot-rotation arithmetic. Single barrier per step.
    auto step = [&](int S0, int S1, int S2, int S3, int dd) {
        // Prefetch plane z+2 into registers (lands in slot S3 at end of step)
        const float* pn = planePtr(dstart + dd + 2);
        const float r0 = pn[go0];
        const float r1 = pn[go1];
        const float r2 = p2 ? pn[go2] : 0.0f;

        // Centers (middle plane S1, row ty+1, cols 2tx+1 / 2tx+2)
        const float cA = rb[S1 * PLANE2 + SROW2 + 1];
        const float cB = rb[S1 * PLANE2 + SROW2 + 2];

        // arg = (KR*n + B)*n + Cm_dist ;  B = -2*KR*c ; Cm0 = KR*c^2
        const ull B2  = pack2((-2.0f * KRC) * cA, (-2.0f * KRC) * cB);
        const ull Cm0 = pack2(KRC * cA * cA, KRC * cB * cB);
        const ull Cm1 = add2(Cm0, KS2);
        const ull Cm2 = add2(Cm1, KS2);
        const ull Cm3 = add2(Cm2, KS2);

        ull num = 0ull, den = 0ull;

        #pragma unroll
        for (int zi = 0; zi < 3; ++zi) {
            const int SB = (zi == 0 ? S0 : (zi == 1 ? S1 : S2)) * PLANE2;
            #pragma unroll
            for (int yi = 0; yi < 3; ++yi) {
                const float* rp = rb + SB + yi * SROW2;   // immediate offsets
                const ull qa = *(const ull*)rp;           // xi=-1 pair (LDS.64)
                const ull qc = *(const ull*)(rp + 2);     // xi=+1 pair (LDS.64)
                float qaL, qaH, qcL, qcH;
                unpack2(qa, qaL, qaH);
                unpack2(qc, qcL, qcH);
                const ull qb = pack2(qaH, qcL);           // xi=0 pair

                const int dyz = (zi - 1) * (zi - 1) + (yi - 1) * (yi - 1);
                const ull Cmid  = (dyz == 0 ? Cm0 : (dyz == 1 ? Cm1 : Cm2));
                const ull Cside = (dyz == 0 ? Cm1 : (dyz == 1 ? Cm2 : Cm3));

                // --- xi = 0 : polynomial path (fma pipe) ---
                {
                    ull t = fma2(KR2, qb, B2);
                    ull u = fma2(t,  qb, add2(Cmid, X0S2));
                    ull p = fma2(C3v, u, C2v);
                    p = fma2(p, u, C1v);
                    p = fma2(p, u, C0v);
                    num = fma2(p, qb, num);
                    den = add2(den, p);
                }
                // --- xi = -1 : MUFU path ---
                {
                    ull t = fma2(KR2, qa, B2);
                    ull u = fma2(t,  qa, Cside);
                    float uL, uH; unpack2(u, uL, uH);
                    ull w = pack2(ex2f(uL), ex2f(uH));
                    num = fma2(w, qa, num);
                    den = add2(den, w);
                }
                // --- xi = +1 : MUFU path ---
                {
                    ull t = fma2(KR2, qc, B2);
                    ull u = fma2(t,  qc, Cside);
                    float uL, uH; unpack2(u, uL, uH);
                    ull w = pack2(ex2f(uL), ex2f(uH));
                    num = fma2(w, qc, num);
                    den = add2(den, w);
                }
            }
        }

        float nL, nH, dL, dH;
        unpack2(num, nL, nH);
        unpack2(den, dL, dH);
        float2 o;
        o.x = __fdividef(nL, dL);   // den >= ~0.84 always (center weight)
        o.y = __fdividef(nH, dH);
        *(float2*)(outp + (size_t)dd * (Hd * Wd)) = o;

        // Commit prefetched plane into the free slot; single barrier orders
        // this step's reads of S0 against next step's writes (S0 becomes free).
        sm[S3 * PLANE2 + i0] = r0;
        sm[S3 * PLANE2 + i1] = r1;
        if (p2) sm[S3 * PLANE2 + i2] = r2;
        __syncthreads();
    };

    #pragma unroll 1
    for (int dq = 0; dq < DCHUNK / NSLOT; ++dq) {
        const int d4 = dq * NSLOT;
        step(0, 1, 2, 3, d4 + 0);
        step(1, 2, 3, 0, d4 + 1);
        step(2, 3, 0, 1, d4 + 2);
        step(3, 0, 1, 2, d4 + 3);
    }
}

extern "C" void kernel_launch(void* const* d_in, const int* in_sizes, int n_in,
                              void* d_out, int out_size) {
    const float* vol = (const float*)d_in[0];
    float* out = (float*)d_out;
    dim3 grid(Wd / TILE_W, Hd / TY, Bd * (Dd / DCHUNK));  // 3 x 24 x 32 = 2304 CTAs
    dim3 block(TX, TY);                                    // 256 threads
    bilat3d_kernel<<<grid, block>>>(vol, out);
}

// round 10
// speedup vs baseline: 1.2240x; 1.0650x over previous
#include <cuda_runtime.h>
#include <cuda_bf16.h>
#include <cstdint>

// Problem constants
#define Wd 192
#define Hd 192
#define Dd 128
#define Bd 2
#define TX 32
#define TY 8
#define NT (TX * TY)             // 256 threads
#define TILE_W 64                // 2 voxels per thread: cols tx and tx+32
#define DCHUNK 8
#define SROWP 34                 // pairs per row: pc in [0,34) covers cols -1..64
#define PLANEP ((TY + 2) * SROWP)   // 340 float2 per z-plane
#define NSLOT 4                  // smem ring depth

typedef unsigned long long ull;

// ---- packed f32x2 helpers (Blackwell sm_103a) ----
__device__ __forceinline__ ull pack2(float lo, float hi) {
    ull r; asm("mov.b64 %0,{%1,%2};" : "=l"(r) : "f"(lo), "f"(hi)); return r;
}
__device__ __forceinline__ void unpack2(ull v, float& lo, float& hi) {
    asm("mov.b64 {%0,%1},%2;" : "=f"(lo), "=f"(hi) : "l"(v));
}
__device__ __forceinline__ ull fma2(ull a, ull b, ull c) {
    ull d; asm("fma.rn.f32x2 %0,%1,%2,%3;" : "=l"(d) : "l"(a), "l"(b), "l"(c)); return d;
}
__device__ __forceinline__ ull add2(ull a, ull b) {
    ull d; asm("add.rn.f32x2 %0,%1,%2;" : "=l"(d) : "l"(a), "l"(b)); return d;
}
__device__ __forceinline__ float ex2f(float x) {
    float y; asm("ex2.approx.ftz.f32 %0, %1;" : "=f"(y) : "f"(x)); return y;
}
__device__ __forceinline__ void cp4(uint32_t saddr, const float* g) {
    asm volatile("cp.async.ca.shared.global [%0], [%1], 4;"
                 :: "r"(saddr), "l"(g) : "memory");
}

// Range-kernel constant: -log2(e) / (2 * 1.2^2)
#define KRC  (-0.50093579f)
// Spatial step in exponent: -log2(e) / (2 * 120^2)
#define KSC  (-5.0093579e-5f)
// Poly expansion shift: u = arg + 0.2505
#define X0S  (0.2505f)
// Degree-3 economized Taylor of 2^x about x0=-0.2505; |u|<=0.2505, abs err ~5e-6
#define PC0 0.8406010f
#define PC1 0.5826630f
#define PC2 0.2024430f
#define PC3 0.0466570f

__global__ __launch_bounds__(NT, 6)
void bilat3d_kernel(const float* __restrict__ in, float* __restrict__ out) {
    // Paired layout: smp[slot][r][pc] = (v[r][w0+pc-1], v[r][w0+pc+31])
    __shared__ __align__(16) float2 smp[NSLOT * PLANEP];

    const int tx  = threadIdx.x;
    const int ty  = threadIdx.y;
    const int tid = ty * TX + tx;
    const int w0  = blockIdx.x * TILE_W;
    const int h0  = blockIdx.y * TY;
    const int bz  = blockIdx.z;
    const int b      = bz / (Dd / DCHUNK);
    const int dstart = (bz % (Dd / DCHUNK)) * DCHUNK;

    const float* base = in + (size_t)b * Dd * Hd * Wd;

    uint32_t smb;
    asm("{ .reg .u64 t; cvta.to.shared.u64 t, %1; cvt.u32.u64 %0, t; }"
        : "=r"(smb) : "l"(smp));

    // ---- dd-invariant gather offsets for the paired fill ----
    auto mkoffs = [&](int i, int& olo, int& ohi) {
        int r  = i / SROWP, pc = i - r * SROWP;
        int gh  = min(max(h0 + r - 1, 0), Hd - 1);
        int glo = min(max(w0 + pc - 1, 0), Wd - 1);
        int ghi = min(w0 + pc + 31, Wd - 1);
        olo = gh * Wd + glo;
        ohi = gh * Wd + ghi;
    };
    const int  i0 = tid, i1 = tid + NT;
    const bool p1 = (i1 < PLANEP);
    int go0lo, go0hi, go1lo = 0, go1hi = 0;
    mkoffs(i0, go0lo, go0hi);
    if (p1) mkoffs(i1, go1lo, go1hi);

    // Async fill of one plane slot (1 cp.async group)
    auto fill = [&](int d, int slot) {
        d = min(max(d, 0), Dd - 1);
        const float* p = base + (size_t)d * Hd * Wd;
        uint32_t a0 = smb + (uint32_t)(slot * PLANEP + i0) * 8u;
        cp4(a0,     p + go0lo);
        cp4(a0 + 4, p + go0hi);
        if (p1) {
            uint32_t a1 = smb + (uint32_t)(slot * PLANEP + i1) * 8u;
            cp4(a1,     p + go1lo);
            cp4(a1 + 4, p + go1hi);
        }
        asm volatile("cp.async.commit_group;" ::: "memory");
    };

    // Prolog: slots 0,1,2 <- planes dstart-1, dstart, dstart+1
    fill(dstart - 1, 0);
    fill(dstart,     1);
    fill(dstart + 1, 2);
    asm volatile("cp.async.wait_group 0;" ::: "memory");
    __syncthreads();

    // Loop-invariant packed constants
    const ull KR2  = pack2(KRC, KRC);
    const ull KS2  = pack2(KSC, KSC);
    const ull X0S2 = pack2(X0S, X0S);
    const ull C0v  = pack2(PC0, PC0);
    const ull C1v  = pack2(PC1, PC1);
    const ull C2v  = pack2(PC2, PC2);
    const ull C3v  = pack2(PC3, PC3);

    const float2* rb = smp + ty * SROWP + tx;   // per-thread pair-row base
    float* outp = out + ((size_t)(b * Dd + dstart) * Hd + (h0 + ty)) * Wd
                      + (w0 + tx);

    // One dd step; S0..S3 compile-time after inlining -> immediate LDS offsets.
    auto step = [&](int S0, int S1, int S2, int S3, int dd) {
        // Kick async fill of plane z+2 into the free slot (overlaps compute)
        fill(dstart + dd + 2, S3);

        // Centers: middle plane, middle row, pair index tx+1 = (v[tx], v[tx+32])
        const ull cq = *(const ull*)(rb + S1 * PLANEP + SROWP + 1);
        float cA, cB; unpack2(cq, cA, cB);

        // arg = (KR*n + B)*n + Cm_dist ;  B = -2*KR*c ; Cm0 = KR*c^2
        const ull B2  = pack2((-2.0f * KRC) * cA, (-2.0f * KRC) * cB);
        const ull Cm0 = pack2(KRC * cA * cA, KRC * cB * cB);
        const ull Cm1 = add2(Cm0, KS2);
        const ull Cm2 = add2(Cm1, KS2);
        const ull Cm3 = add2(Cm2, KS2);
        const ull Cp0 = add2(Cm0, X0S2);   // poly-path constants (pre-shifted)
        const ull Cp1 = add2(Cm1, X0S2);
        const ull Cp2 = add2(Cm2, X0S2);

        ull num = 0ull, den = 0ull;

        #pragma unroll
        for (int zi = 0; zi < 3; ++zi) {
            const int SB = (zi == 0 ? S0 : (zi == 1 ? S1 : S2)) * PLANEP;
            #pragma unroll
            for (int yi = 0; yi < 3; ++yi) {
                const ull* rp = (const ull*)(rb + SB + yi * SROWP);
                const ull qa = rp[0];   // dx=-1 pair: (v[tx-1], v[tx+31])
                const ull qb = rp[1];   // dx= 0 pair: (v[tx  ], v[tx+32])
                const ull qc = rp[2];   // dx=+1 pair: (v[tx+1], v[tx+33])

                const int dyz = (zi - 1) * (zi - 1) + (yi - 1) * (yi - 1);
                const ull Cpm   = (dyz == 0 ? Cp0 : (dyz == 1 ? Cp1 : Cp2));
                const ull Cside = (dyz == 0 ? Cm1 : (dyz == 1 ? Cm2 : Cm3));

                // --- dx = 0 : polynomial path (fma pipe) ---
                {
                    ull t = fma2(KR2, qb, B2);
                    ull u = fma2(t,  qb, Cpm);
                    ull p = fma2(C3v, u, C2v);
                    p = fma2(p, u, C1v);
                    p = fma2(p, u, C0v);
                    num = fma2(p, qb, num);
                    den = add2(den, p);
                }
                // --- dx = -1 : MUFU path ---
                {
                    ull t = fma2(KR2, qa, B2);
                    ull u = fma2(t,  qa, Cside);
                    float uL, uH; unpack2(u, uL, uH);
                    ull w = pack2(ex2f(uL), ex2f(uH));
                    num = fma2(w, qa, num);
                    den = add2(den, w);
                }
                // --- dx = +1 : MUFU path ---
                {
                    ull t = fma2(KR2, qc, B2);
                    ull u = fma2(t,  qc, Cside);
                    float uL, uH; unpack2(u, uL, uH);
                    ull w = pack2(ex2f(uL), ex2f(uH));
                    num = fma2(w, qc, num);
                    den = add2(den, w);
                }
            }
        }

        float nL, nH, dL, dH;
        unpack2(num, nL, nH);
        unpack2(den, dL, dH);
        float* orow = outp + (size_t)dd * (Hd * Wd);
        orow[0]  = __fdividef(nL, dL);   // col tx      (den >= ~0.84 always)
        orow[32] = __fdividef(nH, dH);   // col tx + 32

        // Drain this step's async fill, then release slot S0 for next step.
        asm volatile("cp.async.wait_group 0;" ::: "memory");
        __syncthreads();
    };

    #pragma unroll 1
    for (int dq = 0; dq < DCHUNK / NSLOT; ++dq) {
        const int d4 = dq * NSLOT;
        step(0, 1, 2, 3, d4 + 0);
        step(1, 2, 3, 0, d4 + 1);
        step(2, 3, 0, 1, d4 + 2);
        step(3, 0, 1, 2, d4 + 3);
    }
}

extern "C" void kernel_launch(void* const* d_in, const int* in_sizes, int n_in,
                              void* d_out, int out_size) {
    const float* vol = (const float*)d_in[0];
    float* out = (float*)d_out;
    dim3 grid(Wd / TILE_W, Hd / TY, Bd * (Dd / DCHUNK));  // 3 x 24 x 32 = 2304 CTAs
    dim3 block(TX, TY);                                    // 256 threads
    bilat3d_kernel<<<grid, block>>>(vol, out);
}

// round 12
// speedup vs baseline: 1.3581x; 1.1096x over previous
#include <cuda_runtime.h>
#include <cstdint>

// Problem constants
#define Wd 192
#define Hd 192
#define Dd 128
#define Bd 2
#define TX 32
#define TY 8
#define NT 256
#define TILE_W 64                 // cols tx and tx+32 per thread
#define DCHUNK 16                 // z-planes per CTA
#define SROWP 34                  // pairs per row: pc in [0,34) covers cols -1..64
#define PLANEP ((TY + 2) * SROWP) // 340 float2 per z-plane
#define NSLOT 6                   // smem ring depth (4 live + 2 prefetch)

typedef unsigned long long ull;

// ---- packed f32x2 helpers (Blackwell sm_103a) ----
__device__ __forceinline__ ull pack2(float lo, float hi) {
    ull r; asm("mov.b64 %0,{%1,%2};" : "=l"(r) : "f"(lo), "f"(hi)); return r;
}
__device__ __forceinline__ void unpack2(ull v, float& lo, float& hi) {
    asm("mov.b64 {%0,%1},%2;" : "=f"(lo), "=f"(hi) : "l"(v));
}
__device__ __forceinline__ ull fma2(ull a, ull b, ull c) {
    ull d; asm("fma.rn.f32x2 %0,%1,%2,%3;" : "=l"(d) : "l"(a), "l"(b), "l"(c)); return d;
}
__device__ __forceinline__ ull add2(ull a, ull b) {
    ull d; asm("add.rn.f32x2 %0,%1,%2;" : "=l"(d) : "l"(a), "l"(b)); return d;
}
__device__ __forceinline__ float ex2f(float x) {
    float y; asm("ex2.approx.ftz.f32 %0, %1;" : "=f"(y) : "f"(x)); return y;
}
__device__ __forceinline__ void cp4(uint32_t saddr, const float* g) {
    asm volatile("cp.async.ca.shared.global [%0], [%1], 4;"
                 :: "r"(saddr), "l"(g) : "memory");
}

// Range-kernel constant: -log2(e) / (2 * 1.2^2)
#define KRC  (-0.50093579f)
// Degree-3 poly for 2^x on [-0.501, 0] (x-basis; abs err ~5e-6)
#define QC0 0.99999485f
#define QC1 0.69287016f
#define QC2 0.23750570f
#define QC3 0.04665700f

__global__ __launch_bounds__(NT, 4)
void bilat3d_kernel(const float* __restrict__ in, float* __restrict__ out) {
    // Paired layout: smp[slot][r][pc] = (v[r][w0+pc-1], v[r][w0+pc+31])
    __shared__ __align__(16) float2 smp[NSLOT * PLANEP];

    const int tx  = threadIdx.x;
    const int ty  = threadIdx.y;
    const int tid = ty * TX + tx;
    const int w0  = blockIdx.x * TILE_W;
    const int h0  = blockIdx.y * TY;
    const int bz  = blockIdx.z;
    const int b      = bz / (Dd / DCHUNK);
    const int dstart = (bz % (Dd / DCHUNK)) * DCHUNK;

    const float* base = in + (size_t)b * Dd * Hd * Wd;

    uint32_t smb;
    asm("{ .reg .u64 t; cvta.to.shared.u64 t, %1; cvt.u32.u64 %0, t; }"
        : "=r"(smb) : "l"(smp));

    // dd-invariant gather offsets for the paired fill
    auto mkoffs = [&](int i, int& olo, int& ohi) {
        int r  = i / SROWP, pc = i - r * SROWP;
        int gh  = min(max(h0 + r - 1, 0), Hd - 1);
        int glo = min(max(w0 + pc - 1, 0), Wd - 1);
        int ghi = min(w0 + pc + 31, Wd - 1);
        olo = gh * Wd + glo;
        ohi = gh * Wd + ghi;
    };
    const int  i0 = tid, i1 = tid + NT;
    const bool p1 = (i1 < PLANEP);
    int go0lo, go0hi, go1lo = 0, go1hi = 0;
    mkoffs(i0, go0lo, go0hi);
    if (p1) mkoffs(i1, go1lo, go1hi);

    // Async fill of one plane slot
    auto fill = [&](int d, int slot) {
        d = min(max(d, 0), Dd - 1);
        const float* p = base + (size_t)d * Hd * Wd;
        uint32_t a0 = smb + (uint32_t)(slot * PLANEP + i0) * 8u;
        cp4(a0,     p + go0lo);
        cp4(a0 + 4, p + go0hi);
        if (p1) {
            uint32_t a1 = smb + (uint32_t)(slot * PLANEP + i1) * 8u;
            cp4(a1,     p + go1lo);
            cp4(a1 + 4, p + go1hi);
        }
        asm volatile("cp.async.commit_group;" ::: "memory");
    };

    // Prolog: slots 0..3 <- planes dstart-1 .. dstart+2
    fill(dstart - 1, 0);
    fill(dstart,     1);
    fill(dstart + 1, 2);
    fill(dstart + 2, 3);
    asm volatile("cp.async.wait_group 0;" ::: "memory");
    __syncthreads();

    const ull KR2 = pack2(KRC, KRC);
    const ull Q0v = pack2(QC0, QC0);
    const ull Q1v = pack2(QC1, QC1);
    const ull Q2v = pack2(QC2, QC2);
    const ull Q3v = pack2(QC3, QC3);

    const float2* rb = smp + ty * SROWP + tx;   // per-thread pair-row base
    float* outp = out + ((size_t)(b * Dd + dstart) * Hd + (h0 + ty)) * Wd
                      + (w0 + tx);

    // One row-triple applied to one z-output (3 neighbors of that row)
    auto apply = [&](ull qa, ull qb, ull qc, ull B2, ull Cm0,
                     ull& num, ull& den) {
        // dx = 0: polynomial path (fma pipe)
        ull t = fma2(KR2, qb, B2);
        ull u = fma2(t,  qb, Cm0);
        ull p = fma2(Q3v, u, Q2v);
        p = fma2(p, u, Q1v);
        p = fma2(p, u, Q0v);
        num = fma2(p, qb, num);
        den = add2(den, p);
        // dx = -1: MUFU path
        t = fma2(KR2, qa, B2);
        u = fma2(t,  qa, Cm0);
        float uL, uH; unpack2(u, uL, uH);
        ull w = pack2(ex2f(uL), ex2f(uH));
        num = fma2(w, qa, num);
        den = add2(den, w);
        // dx = +1: MUFU path
        t = fma2(KR2, qc, B2);
        u = fma2(t,  qc, Cm0);
        unpack2(u, uL, uH);
        w = pack2(ex2f(uL), ex2f(uH));
        num = fma2(w, qc, num);
        den = add2(den, w);
    };

    // One step = 2 z-outputs (z0, z0+1) sharing the 12 loaded rows.
    // S0..S3 = slots of planes z0-1..z0+2 (compile-time). P0,P1 = prefetch slots.
    auto step = [&](int S0, int S1, int S2, int S3, int P0, int P1,
                    int zc, bool pf) {
        if (pf) { fill(dstart + zc + 3, P0); fill(dstart + zc + 4, P1); }

        // Centers: pair idx tx+1 of middle planes
        const ull cqA = *(const ull*)(rb + S1 * PLANEP + SROWP + 1);
        const ull cqB = *(const ull*)(rb + S2 * PLANEP + SROWP + 1);
        float cAa, cAb, cBa, cBb;
        unpack2(cqA, cAa, cAb);
        unpack2(cqB, cBa, cBb);
        // arg = (KR*n + B)*n + Cm0 = KR*(n-c)^2 ; B = -2*KR*c ; Cm0 = KR*c^2
        const ull B2A = pack2((-2.0f * KRC) * cAa, (-2.0f * KRC) * cAb);
        const ull CmA = pack2(KRC * cAa * cAa, KRC * cAb * cAb);
        const ull B2B = pack2((-2.0f * KRC) * cBa, (-2.0f * KRC) * cBb);
        const ull CmB = pack2(KRC * cBa * cBa, KRC * cBb * cBb);

        ull numA = 0ull, denA = 0ull, numB = 0ull, denB = 0ull;

        #pragma unroll
        for (int zp = 0; zp < 4; ++zp) {
            const int SS = (zp == 0 ? S0 : zp == 1 ? S1 : zp == 2 ? S2 : S3);
            #pragma unroll
            for (int yi = 0; yi < 3; ++yi) {
                const ull* rp = (const ull*)(rb + SS * PLANEP + yi * SROWP);
                const ull qa = rp[0];   // dx=-1 pair
                const ull qb = rp[1];   // dx= 0 pair
                const ull qc = rp[2];   // dx=+1 pair
                if (zp < 3) apply(qa, qb, qc, B2A, CmA, numA, denA);
                if (zp > 0) apply(qa, qb, qc, B2B, CmB, numB, denB);
            }
        }

        float nL, nH, dL, dH;
        float* oA = outp + (size_t)zc * (Hd * Wd);
        unpack2(numA, nL, nH); unpack2(denA, dL, dH);
        oA[0]  = __fdividef(nL, dL);          // den >= ~0.88 always
        oA[32] = __fdividef(nH, dH);
        float* oB = oA + (Hd * Wd);
        unpack2(numB, nL, nH); unpack2(denB, dL, dH);
        oB[0]  = __fdividef(nL, dL);
        oB[32] = __fdividef(nH, dH);

        asm volatile("cp.async.wait_group 0;" ::: "memory");
        __syncthreads();
    };

    // Slot pattern period 3 (plane p -> slot (p+1) mod 6); 8 steps cover z 0..15
    #pragma unroll 1
    for (int g = 0; g < 2; ++g) {
        const int zc = g * 6;
        step(0, 1, 2, 3, 4, 5, zc + 0, true);
        step(2, 3, 4, 5, 0, 1, zc + 2, true);
        step(4, 5, 0, 1, 2, 3, zc + 4, true);
    }
    step(0, 1, 2, 3, 4, 5, 12, true);
    step(2, 3, 4, 5, 0, 1, 14, false);
}

extern "C" void kernel_launch(void* const* d_in, const int* in_sizes, int n_in,
                              void* d_out, int out_size) {
    const float* vol = (const float*)d_in[0];
    float* out = (float*)d_out;
    dim3 grid(Wd / TILE_W, Hd / TY, Bd * (Dd / DCHUNK));  // 3 x 24 x 16 = 1152 CTAs
    dim3 block(TX, TY);                                    // 256 threads
    bilat3d_kernel<<<grid, block>>>(vol, out);
}